// round 1
// baseline (speedup 1.0000x reference)
#include <cuda_runtime.h>

// Problem constants
#define DIMN   16
#define SECN   16
#define SUBN   16
#define EN     256
#define BATCHN 128
#define SLN    64

// Output layout (flattened reference tuple, float32)
#define OFF_TZ1  0
#define OFF_TZ2  1024
#define OFF_FWD  2048
#define OFF_EQ   18432
#define OFF_ATT  18433
#define OFF_ORTH 35841
#define OFF_PAR  35842
#define OFF_COM  35843
#define OFF_SPA  35844
#define OFF_SEC  35845
#define OFF_SUB  35846

// Scratch (static device allocations are allowed)
__device__ float  g_syms[EN * 256];            // expm(ge)
__device__ float  g_u[EN * BATCHN * DIMN];     // normalized diff rows
__device__ float  g_w[SLN * EN];               // switch*fprob weights
__device__ float  g_S[SLN * 256];              // S matrices
__device__ float  g_inv[SLN * 256];            // expm(-S)
__device__ double g_acc[8];                    // 0 sparse, 1 parallel, 2 orth, 3 commut, 4 sector

// ---------------------------------------------------------------------------
__global__ void k_zero() {
    if (threadIdx.x < 8) g_acc[threadIdx.x] = 0.0;
}

// ---------------------------------------------------------------------------
// expm of 16x16 matrices: scaling & squaring + order-12 Taylor (Horner).
// mode 0: src = ext_src (ge),  dst = g_syms
// mode 1: src = g_S,           dst = ext_dst (out + OFF_FWD)
// mode 2: src = g_S,           dst = g_inv
__global__ void k_expm(const float* __restrict__ ext_src, float* __restrict__ ext_dst,
                       int mode, float sign) {
    __shared__ float Bm[256], P[256], T[256], red[16];
    __shared__ int s_sh;
    const int tid = threadIdx.x;
    const int r = tid >> 4, c = tid & 15;

    const float* src = (mode == 0) ? ext_src : g_S;
    float* dst = (mode == 0) ? g_syms : ((mode == 1) ? ext_dst : g_inv);

    float a = sign * src[blockIdx.x * 256 + tid];

    // inf-norm = max row sum of |A|
    T[tid] = fabsf(a);
    __syncthreads();
    if (tid < 16) {
        float rs = 0.f;
        #pragma unroll
        for (int k = 0; k < 16; k++) rs += T[tid * 16 + k];
        red[tid] = rs;
    }
    __syncthreads();
    if (tid == 0) {
        float mx = 0.f;
        #pragma unroll
        for (int k = 0; k < 16; k++) mx = fmaxf(mx, red[k]);
        int s = 0;
        while (mx > 0.25f && s < 48) { mx *= 0.5f; s++; }
        s_sh = s;
    }
    __syncthreads();
    const int s = s_sh;

    float b = a * exp2f(-(float)s);
    Bm[tid] = b;
    P[tid] = b * (1.0f / 12.0f) + ((r == c) ? 1.0f : 0.0f);

    for (int k = 11; k >= 1; k--) {
        __syncthreads();
        float acc = 0.f;
        #pragma unroll
        for (int j = 0; j < 16; j++) acc += Bm[r * 16 + j] * P[j * 16 + c];
        __syncthreads();
        P[tid] = acc * (1.0f / (float)k) + ((r == c) ? 1.0f : 0.0f);
    }
    for (int i = 0; i < s; i++) {
        __syncthreads();
        float acc = 0.f;
        #pragma unroll
        for (int j = 0; j < 16; j++) acc += P[r * 16 + j] * P[j * 16 + c];
        __syncthreads();
        P[tid] = acc;
    }
    __syncthreads();
    dst[blockIdx.x * 256 + tid] = P[tid];
}

// ---------------------------------------------------------------------------
// diff[e,b,:] = z[b] - z[b] @ syms[e]; accumulate sparse; store normalized rows.
__global__ void k_diff(const float* __restrict__ z) {
    __shared__ float sy[256];
    __shared__ float zsh[BATCHN * 16];
    __shared__ float redsh[128];
    const int e = blockIdx.x, tid = threadIdx.x;   // 128 threads

    sy[tid] = g_syms[e * 256 + tid];
    sy[tid + 128] = g_syms[e * 256 + tid + 128];
    #pragma unroll
    for (int i = 0; i < 16; i++) zsh[tid + 128 * i] = z[tid + 128 * i];
    __syncthreads();

    const int b = tid;
    float zr[16];
    #pragma unroll
    for (int d = 0; d < 16; d++) zr[d] = zsh[b * 16 + d];

    float dv[16];
    float s2 = 0.f, mx = 0.f;
    #pragma unroll
    for (int d = 0; d < 16; d++) {
        float dot0 = 0.f, dot1 = 0.f;
        #pragma unroll
        for (int k = 0; k < 16; k += 2) {
            dot0 += zr[k] * sy[k * 16 + d];
            dot1 += zr[k + 1] * sy[(k + 1) * 16 + d];
        }
        float v = zr[d] - (dot0 + dot1);
        dv[d] = v;
        float q = v * v;
        s2 += q;
        mx = fmaxf(mx, q);
    }
    float sp = s2 - mx;
    sp = sp * sp;

    redsh[tid] = sp;
    __syncthreads();
    for (int off = 64; off > 0; off >>= 1) {
        if (tid < off) redsh[tid] += redsh[tid + off];
        __syncthreads();
    }
    if (tid == 0) atomicAdd(&g_acc[0], (double)redsh[0]);

    float inv = rsqrtf(s2);
    #pragma unroll
    for (int d = 0; d < 16; d++) g_u[(e * 128 + b) * 16 + d] = dv[d] * inv;
}

// ---------------------------------------------------------------------------
// parallel: per sector (2048 unit vectors dim 16), sum of -log(cos^2 + 1e-9)
// over all pairs. 128x128 tiles, upper-triangular tiles, off-diag doubled.
__global__ void k_parallel() {
    __shared__ float As[16 * 129], Bs[16 * 129];
    __shared__ float rsh[256];
    const int blk = blockIdx.x;
    const int sec = blk / 136;
    int p = blk % 136;
    int ti = 0;
    while (p >= 16 - ti) { p -= 16 - ti; ti++; }
    const int tj = ti + p;
    const int tid = threadIdx.x;

    const float* baseA = g_u + (sec * 2048 + ti * 128) * 16;
    const float* baseB = g_u + (sec * 2048 + tj * 128) * 16;
    for (int i = tid; i < 2048; i += 256) {
        int m = i >> 4, k = i & 15;
        As[k * 129 + m] = baseA[i];
        Bs[k * 129 + m] = baseB[i];
    }
    __syncthreads();

    float acc = 0.f;
    for (int idx = tid; idx < 16384; idx += 256) {
        int m = idx >> 7, n = idx & 127;
        float d0 = 0.f, d1 = 0.f;
        #pragma unroll
        for (int k = 0; k < 16; k += 2) {
            d0 += As[k * 129 + m] * Bs[k * 129 + n];
            d1 += As[(k + 1) * 129 + m] * Bs[(k + 1) * 129 + n];
        }
        float t = d0 + d1;
        acc -= __logf(t * t + 1e-9f);
    }
    acc *= (ti == tj) ? 1.0f : 2.0f;

    rsh[tid] = acc;
    __syncthreads();
    for (int off = 128; off > 0; off >>= 1) {
        if (tid < off) rsh[tid] += rsh[tid + off];
        __syncthreads();
    }
    if (tid == 0) atomicAdd(&g_acc[1], (double)rsh[0]);
}

// ---------------------------------------------------------------------------
// orth: cross-sector cos^2 sums over selected (per sec_idx) rows. 120 pairs s<t.
__global__ void k_orth(const int* __restrict__ sidx) {
    __shared__ float As[16 * 129], Bs[16 * 129];
    __shared__ float rsh[256];
    int p = blockIdx.x;
    int s = 0;
    while (p >= 15 - s) { p -= 15 - s; s++; }
    const int t2 = s + 1 + p;
    const int tid = threadIdx.x;

    const int ea = s * 16 + sidx[s];
    const int eb = t2 * 16 + sidx[t2];
    const float* baseA = g_u + ea * 128 * 16;
    const float* baseB = g_u + eb * 128 * 16;
    for (int i = tid; i < 2048; i += 256) {
        int m = i >> 4, k = i & 15;
        As[k * 129 + m] = baseA[i];
        Bs[k * 129 + m] = baseB[i];
    }
    __syncthreads();

    float acc = 0.f;
    for (int idx = tid; idx < 16384; idx += 256) {
        int m = idx >> 7, n = idx & 127;
        float d0 = 0.f, d1 = 0.f;
        #pragma unroll
        for (int k = 0; k < 16; k += 2) {
            d0 += As[k * 129 + m] * Bs[k * 129 + n];
            d1 += As[(k + 1) * 129 + m] * Bs[(k + 1) * 129 + n];
        }
        float t = d0 + d1;
        acc += t * t;
    }
    acc *= 2.0f;  // symmetric pair (s,t) and (t,s)

    rsh[tid] = acc;
    __syncthreads();
    for (int off = 128; off > 0; off >>= 1) {
        if (tid < off) rsh[tid] += rsh[tid + off];
        __syncthreads();
    }
    if (tid == 0) atomicAdd(&g_acc[2], (double)rsh[0]);
}

// ---------------------------------------------------------------------------
// commut: c[a,b] = 2*sum_{r,s}(R[a,r,b,s]-R[b,r,a,s])^2,
// R[a,r,b,s] = sum_c ge[a,r,c]*ge[16c,b,s]; weighted by (120 - pair_index).
__global__ void k_commut(const float* __restrict__ ge) {
    __shared__ float gA[256], gB[256], gCa[256], gCb[256], rsh[256];
    int p = blockIdx.x;
    const int j = blockIdx.x;
    int a = 0;
    while (p >= 15 - a) { p -= 15 - a; a++; }
    const int b2 = a + 1 + p;
    const int tid = threadIdx.x;
    const int r = tid >> 4, s = tid & 15;

    gA[tid] = ge[a * 256 + tid];
    gB[tid] = ge[b2 * 256 + tid];
    {
        int c = tid >> 4, ss = tid & 15;
        gCa[tid] = ge[(c * 16) * 256 + a * 16 + ss];
        gCb[tid] = ge[(c * 16) * 256 + b2 * 16 + ss];
    }
    __syncthreads();

    float R1 = 0.f, R2 = 0.f;
    #pragma unroll
    for (int cc = 0; cc < 16; cc++) {
        R1 += gA[r * 16 + cc] * gCb[cc * 16 + s];
        R2 += gB[r * 16 + cc] * gCa[cc * 16 + s];
    }
    float d = R1 - R2;
    rsh[tid] = d * d;
    __syncthreads();
    for (int off = 128; off > 0; off >>= 1) {
        if (tid < off) rsh[tid] += rsh[tid + off];
        __syncthreads();
    }
    if (tid == 0) atomicAdd(&g_acc[3], (double)(2.0f * rsh[0]) * (double)(120 - j));
}

// ---------------------------------------------------------------------------
// Linear head + softmaxes + gumbel switch + fprob; writes attn_score + g_w;
// accumulates sector_loss.
__global__ void k_head(const float* __restrict__ mean, const float* __restrict__ logvar,
                       const float* __restrict__ z, const float* __restrict__ lw,
                       const float* __restrict__ lb, const float* __restrict__ gn,
                       float* __restrict__ out) {
    __shared__ float feat[64], prob[288], sw[16];
    const int b = blockIdx.x, t = threadIdx.x;  // 128 threads

    if (t < 64) {
        float v;
        if (t < 16)       v = mean[b * 16 + t];
        else if (t < 32)  v = expf(0.5f * logvar[b * 16 + (t - 16)]);
        else if (t < 48)  v = mean[(64 + b) * 16 + (t - 32)];
        else              v = expf(0.5f * mean[(64 + b) * 16 + (t - 48)]);
        feat[t] = v;
    }
    __syncthreads();

    for (int jj = t; jj < 288; jj += 128) {
        float acc = lb[jj];
        const float* wrow = lw + jj * 64;
        #pragma unroll
        for (int k = 0; k < 64; k++) acc += feat[k] * wrow[k];
        prob[jj] = acc;
    }
    __syncthreads();

    if (t < 16) {
        const int s = t;
        float l0 = prob[2 * s], l1 = prob[2 * s + 1];
        // p = softmax([l0,l1])
        float m = fmaxf(l0, l1);
        float e0 = expf(l0 - m), e1 = expf(l1 - m);
        float Z = e0 + e1;
        float p0 = e0 / Z, p1 = e1 / Z;
        // ls = log_softmax(p)  (reference quirk)
        float mm = fmaxf(p0, p1);
        float lse = mm + logf(expf(p0 - mm) + expf(p1 - mm));
        float zd = z[b * 16 + s] - z[(64 + b) * 16 + s];
        int tgt = (fabsf(zd) > 0.2f) ? 1 : 0;
        float lst = (tgt ? p1 : p0) - lse;
        atomicAdd(&g_acc[4], (double)(-lst));
        // gumbel attn (tau = 1e-4, saturates)
        float g0 = gn[(b * 16 + s) * 2], g1 = gn[(b * 16 + s) * 2 + 1];
        const float TAUF = 0.0001f;
        float d0 = (l0 + g0) / TAUF, d1 = (l1 + g1) / TAUF;
        float m2 = fmaxf(d0, d1);
        float a0 = expf(d0 - m2), a1 = expf(d1 - m2);
        float attn1 = a1 / (a0 + a1);   // switch == attn[:,1] always
        sw[s] = attn1;
        out[OFF_ATT + b * 272 + s] = attn1;
    }
    __syncthreads();

    if (t < 16) {
        const int s = t;
        float mx = -1e30f;
        #pragma unroll
        for (int u = 0; u < 16; u++) mx = fmaxf(mx, prob[32 + s * 16 + u]);
        float ex[16];
        float sum = 0.f;
        #pragma unroll
        for (int u = 0; u < 16; u++) {
            ex[u] = expf(prob[32 + s * 16 + u] - mx);
            sum += ex[u];
        }
        float inv = 1.0f / sum;
        float swv = sw[s];
        #pragma unroll
        for (int u = 0; u < 16; u++) {
            float f = ex[u] * inv;
            out[OFF_ATT + b * 272 + 16 + s * 16 + u] = f;
            g_w[b * 256 + s * 16 + u] = f * swv;
        }
    }
}

// ---------------------------------------------------------------------------
// sub_syms[b,s] = sum_u w[b,s*16+u]*ge[s*16+u]; S[b] = sum_s sub_syms[b,s].
__global__ void k_subsyms(const float* __restrict__ ge, float* __restrict__ out) {
    const int b = blockIdx.x, tid = threadIdx.x;  // 256 threads
    __shared__ float wsh[256];
    wsh[tid] = g_w[b * 256 + tid];
    __syncthreads();

    float Sacc = 0.f;
    #pragma unroll 1
    for (int s = 0; s < 16; s++) {
        float a = 0.f;
        #pragma unroll
        for (int u = 0; u < 16; u++)
            a += wsh[s * 16 + u] * ge[(s * 16 + u) * 256 + tid];
        out[OFF_SUB + b * 4096 + s * 256 + tid] = a;
        Sacc += a;
    }
    g_S[b * 256 + tid] = Sacc;
}

// ---------------------------------------------------------------------------
// tz1/tz2 and equivariant.
__global__ void k_tz(const float* __restrict__ z, float* __restrict__ out) {
    __shared__ float rsh[1024];
    const int t = threadIdx.x;  // 1024 threads
    const int b = t >> 4, d = t & 15;
    const float* fwd = out + OFF_FWD;

    float t1 = 0.f, t2 = 0.f;
    #pragma unroll
    for (int k = 0; k < 16; k++) {
        t1 += z[b * 16 + k] * fwd[b * 256 + k * 16 + d];
        t2 += z[(64 + b) * 16 + k] * g_inv[b * 256 + k * 16 + d];
    }
    out[OFF_TZ1 + b * 16 + d] = t1;
    out[OFF_TZ2 + b * 16 + d] = t2;

    float e1 = t2 - z[b * 16 + d];
    float e2 = t1 - z[(64 + b) * 16 + d];
    rsh[t] = e1 * e1 + e2 * e2;
    __syncthreads();
    for (int off = 512; off > 0; off >>= 1) {
        if (t < off) rsh[t] += rsh[t + off];
        __syncthreads();
    }
    if (t == 0) out[OFF_EQ] = rsh[0] * (1.0f / 1024.0f);
}

// ---------------------------------------------------------------------------
__global__ void k_final(float* __restrict__ out) {
    if (threadIdx.x == 0) {
        out[OFF_SPA]  = (float)(g_acc[0] / 32768.0);
        out[OFF_PAR]  = (float)(g_acc[1] / 67108864.0);
        out[OFF_ORTH] = (float)(g_acc[2] / 4194304.0);
        out[OFF_COM]  = (float)(g_acc[3] / 16777216.0);
        out[OFF_SEC]  = (float)(g_acc[4] / 64.0);
    }
}

// ---------------------------------------------------------------------------
extern "C" void kernel_launch(void* const* d_in, const int* in_sizes, int n_in,
                              void* d_out, int out_size) {
    const float* mean   = (const float*)d_in[0];
    const float* logvar = (const float*)d_in[1];
    const float* z      = (const float*)d_in[2];
    const float* ge     = (const float*)d_in[3];
    const float* lw     = (const float*)d_in[4];
    const float* lb     = (const float*)d_in[5];
    const float* gn     = (const float*)d_in[6];
    const int*   sidx   = (const int*)d_in[7];
    float* out = (float*)d_out;

    k_zero<<<1, 32>>>();
    k_expm<<<256, 256>>>(ge, nullptr, 0, 1.0f);          // syms = expm(ge)
    k_diff<<<256, 128>>>(z);                             // diff, sparse, normalize
    k_parallel<<<16 * 136, 256>>>();                     // parallel term
    k_orth<<<120, 256>>>(sidx);                          // orth term
    k_commut<<<120, 256>>>(ge);                          // commut term
    k_head<<<64, 128>>>(mean, logvar, z, lw, lb, gn, out);
    k_subsyms<<<64, 256>>>(ge, out);                     // sub_syms + S
    k_expm<<<64, 256>>>(nullptr, out + OFF_FWD, 1, 1.0f);  // fwd_syms
    k_expm<<<64, 256>>>(nullptr, nullptr, 2, -1.0f);       // inv_syms
    k_tz<<<1, 1024>>>(z, out);                           // tz1, tz2, equivariant
    k_final<<<1, 32>>>(out);                             // scalars
}

// round 4
// speedup vs baseline: 1.3882x; 1.3882x over previous
#include <cuda_runtime.h>

// Problem constants
#define DIMN   16
#define SECN   16
#define SUBN   16
#define EN     256
#define BATCHN 128
#define SLN    64

// Output layout (flattened reference tuple, float32)
#define OFF_TZ1  0
#define OFF_TZ2  1024
#define OFF_FWD  2048
#define OFF_EQ   18432
#define OFF_ATT  18433
#define OFF_ORTH 35841
#define OFF_PAR  35842
#define OFF_COM  35843
#define OFF_SPA  35844
#define OFF_SEC  35845
#define OFF_SUB  35846

// Scratch
__device__ float  g_syms[EN * 256];            // expm(ge)
__device__ float  g_u[EN * BATCHN * DIMN];     // normalized diff rows
__device__ float  g_w[SLN * EN];               // switch*fprob weights
__device__ float  g_S[SLN * 256];              // S matrices
__device__ float  g_inv[SLN * 256];            // expm(-S)
__device__ double g_acc[8];                    // 0 sparse, 1 parallel, 2 orth, 3 commut, 4 sector

// ---------------------------------------------------------------------------
// f32x2 packed helpers (sm_103a FFMA2 path)
__device__ __forceinline__ unsigned long long pk2(float lo, float hi) {
    unsigned long long r;
    asm("mov.b64 %0, {%1, %2};" : "=l"(r) : "f"(lo), "f"(hi));
    return r;
}
__device__ __forceinline__ void upk2(float& lo, float& hi, unsigned long long v) {
    asm("mov.b64 {%0, %1}, %2;" : "=f"(lo), "=f"(hi) : "l"(v));
}
__device__ __forceinline__ unsigned long long ffma2(unsigned long long a,
                                                    unsigned long long b,
                                                    unsigned long long c) {
    unsigned long long d;
    asm("fma.rn.f32x2 %0, %1, %2, %3;" : "=l"(d) : "l"(a), "l"(b), "l"(c));
    return d;
}

// ---------------------------------------------------------------------------
// expm body: 16x16 scaling & squaring + order-12 Taylor Horner.
__device__ __forceinline__ void expm_body(const float* __restrict__ src,
                                          float* __restrict__ dst, float sign) {
    __shared__ float Bm[256], P[256], T[256], red[16];
    __shared__ int s_sh;
    const int tid = threadIdx.x;
    const int r = tid >> 4, c = tid & 15;

    float a = sign * src[tid];

    T[tid] = fabsf(a);
    __syncthreads();
    if (tid < 16) {
        float rs = 0.f;
        #pragma unroll
        for (int k = 0; k < 16; k++) rs += T[tid * 16 + k];
        red[tid] = rs;
    }
    __syncthreads();
    if (tid == 0) {
        float mx = 0.f;
        #pragma unroll
        for (int k = 0; k < 16; k++) mx = fmaxf(mx, red[k]);
        int s = 0;
        while (mx > 0.25f && s < 48) { mx *= 0.5f; s++; }
        s_sh = s;
    }
    __syncthreads();
    const int s = s_sh;

    float b = a * exp2f(-(float)s);
    Bm[tid] = b;
    P[tid] = b * (1.0f / 12.0f) + ((r == c) ? 1.0f : 0.0f);

    for (int k = 11; k >= 1; k--) {
        __syncthreads();
        float acc = 0.f;
        #pragma unroll
        for (int j = 0; j < 16; j++) acc += Bm[r * 16 + j] * P[j * 16 + c];
        __syncthreads();
        P[tid] = acc * (1.0f / (float)k) + ((r == c) ? 1.0f : 0.0f);
    }
    for (int i = 0; i < s; i++) {
        __syncthreads();
        float acc = 0.f;
        #pragma unroll
        for (int j = 0; j < 16; j++) acc += P[r * 16 + j] * P[j * 16 + c];
        __syncthreads();
        P[tid] = acc;
    }
    __syncthreads();
    dst[tid] = P[tid];
}

// expm(ge) -> g_syms ; block 0 also zeroes accumulators
__global__ void k_expm_ge(const float* __restrict__ ge) {
    if (blockIdx.x == 0 && threadIdx.x < 8) g_acc[threadIdx.x] = 0.0;
    expm_body(ge + blockIdx.x * 256, g_syms + blockIdx.x * 256, 1.0f);
}

// expm(+/-S): blocks 0-63 -> fwd_syms (out), blocks 64-127 -> g_inv
__global__ void k_expm_S(float* __restrict__ out) {
    const int b = blockIdx.x & 63;
    const bool inv = blockIdx.x >= 64;
    float* dst = inv ? (g_inv + b * 256) : (out + OFF_FWD + b * 256);
    expm_body(g_S + b * 256, dst, inv ? -1.0f : 1.0f);
}

// ---------------------------------------------------------------------------
// diff[e,b,:] = z[b] - z[b] @ syms[e]; accumulate sparse; store normalized rows.
__global__ void k_diff(const float* __restrict__ z) {
    __shared__ float sy[256];
    __shared__ float zsh[BATCHN * 16];
    __shared__ float redsh[128];
    const int e = blockIdx.x, tid = threadIdx.x;   // 128 threads

    sy[tid] = g_syms[e * 256 + tid];
    sy[tid + 128] = g_syms[e * 256 + tid + 128];
    #pragma unroll
    for (int i = 0; i < 16; i++) zsh[tid + 128 * i] = z[tid + 128 * i];
    __syncthreads();

    const int b = tid;
    float zr[16];
    #pragma unroll
    for (int d = 0; d < 16; d++) zr[d] = zsh[b * 16 + d];

    float dv[16];
    float s2 = 0.f, mx = 0.f;
    #pragma unroll
    for (int d = 0; d < 16; d++) {
        float dot0 = 0.f, dot1 = 0.f;
        #pragma unroll
        for (int k = 0; k < 16; k += 2) {
            dot0 += zr[k] * sy[k * 16 + d];
            dot1 += zr[k + 1] * sy[(k + 1) * 16 + d];
        }
        float v = zr[d] - (dot0 + dot1);
        dv[d] = v;
        float q = v * v;
        s2 += q;
        mx = fmaxf(mx, q);
    }
    float sp = s2 - mx;
    sp = sp * sp;

    redsh[tid] = sp;
    __syncthreads();
    for (int off = 64; off > 0; off >>= 1) {
        if (tid < off) redsh[tid] += redsh[tid + off];
        __syncthreads();
    }
    if (tid == 0) atomicAdd(&g_acc[0], (double)redsh[0]);

    float inv = rsqrtf(s2);
    #pragma unroll
    for (int d = 0; d < 16; d++) g_u[(e * 128 + b) * 16 + d] = dv[d] * inv;
}

// ---------------------------------------------------------------------------
// Gram kernel: 128x128 tiles of cosine products over unit rows of g_u.
// Blocks [0, 2176): parallel term (16 sectors x 136 triangular tile pairs),
//                   entry = -log(cos^2 + 1e-9), off-diag tiles doubled.
// Blocks [2176, 2296): orth term (120 sector pairs via sec_idx), entry = cos^2, x2.
// 256 threads, 8x8 register blocking, f32x2 packed FMA.
__global__ void __launch_bounds__(256) k_gram(const int* __restrict__ sidx) {
    __shared__ float As[16 * 128], Bs[16 * 128];
    __shared__ float rsh[256];
    const int tid = threadIdx.x;
    const int bi = blockIdx.x;
    const bool isOrth = bi >= 2176;

    const float* baseA;
    const float* baseB;
    float mult;
    if (!isOrth) {
        const int sec = bi / 136;
        int p = bi % 136;
        int ti = 0;
        while (p >= 16 - ti) { p -= 16 - ti; ti++; }
        const int tj = ti + p;
        baseA = g_u + (sec * 2048 + ti * 128) * 16;
        baseB = g_u + (sec * 2048 + tj * 128) * 16;
        mult = (ti == tj) ? 1.0f : 2.0f;
    } else {
        int p = bi - 2176;
        int s = 0;
        while (p >= 15 - s) { p -= 15 - s; s++; }
        const int t2 = s + 1 + p;
        baseA = g_u + (s * 16 + sidx[s]) * 2048;
        baseB = g_u + (t2 * 16 + sidx[t2]) * 2048;
        mult = 2.0f;
    }

    // Load both 128x16 tiles, transposed to [k][m] layout.
    {
        const float4* a4 = (const float4*)baseA;
        const float4* b4 = (const float4*)baseB;
        #pragma unroll
        for (int i = 0; i < 2; i++) {
            const int idx = tid * 2 + i;     // 512 float4 per matrix
            const float4 va = a4[idx];
            const float4 vb = b4[idx];
            const int m = idx >> 2;
            const int k = (idx & 3) * 4;
            As[(k + 0) * 128 + m] = va.x; As[(k + 1) * 128 + m] = va.y;
            As[(k + 2) * 128 + m] = va.z; As[(k + 3) * 128 + m] = va.w;
            Bs[(k + 0) * 128 + m] = vb.x; Bs[(k + 1) * 128 + m] = vb.y;
            Bs[(k + 2) * 128 + m] = vb.z; Bs[(k + 3) * 128 + m] = vb.w;
        }
    }
    __syncthreads();

    const int tx = tid & 15, ty = tid >> 4;
    unsigned long long acc[8][4];
    #pragma unroll
    for (int m = 0; m < 8; m++)
        #pragma unroll
        for (int n = 0; n < 4; n++) acc[m][n] = 0ULL;

    #pragma unroll
    for (int k = 0; k < 16; k++) {
        const float4 a0 = *(const float4*)(As + k * 128 + ty * 8);
        const float4 a1 = *(const float4*)(As + k * 128 + ty * 8 + 4);
        const float4 b0 = *(const float4*)(Bs + k * 128 + tx * 8);
        const float4 b1 = *(const float4*)(Bs + k * 128 + tx * 8 + 4);
        unsigned long long bp[4];
        bp[0] = pk2(b0.x, b0.y); bp[1] = pk2(b0.z, b0.w);
        bp[2] = pk2(b1.x, b1.y); bp[3] = pk2(b1.z, b1.w);
        const float av[8] = {a0.x, a0.y, a0.z, a0.w, a1.x, a1.y, a1.z, a1.w};
        #pragma unroll
        for (int m = 0; m < 8; m++) {
            const unsigned long long am = pk2(av[m], av[m]);
            #pragma unroll
            for (int n = 0; n < 4; n++) acc[m][n] = ffma2(am, bp[n], acc[m][n]);
        }
    }

    float local = 0.f;
    #pragma unroll
    for (int m = 0; m < 8; m++) {
        #pragma unroll
        for (int n = 0; n < 4; n++) {
            float lo, hi;
            upk2(lo, hi, acc[m][n]);
            if (isOrth) {
                local += lo * lo + hi * hi;
            } else {
                local -= __logf(fmaf(lo, lo, 1e-9f));
                local -= __logf(fmaf(hi, hi, 1e-9f));
            }
        }
    }
    local *= mult;

    rsh[tid] = local;
    __syncthreads();
    for (int off = 128; off > 0; off >>= 1) {
        if (tid < off) rsh[tid] += rsh[tid + off];
        __syncthreads();
    }
    if (tid == 0) atomicAdd(&g_acc[isOrth ? 2 : 1], (double)rsh[0]);
}

// ---------------------------------------------------------------------------
// Merged: blocks [0,120) commut pairs; blocks [120,184) linear head rows.
__global__ void k_misc(const float* __restrict__ ge,
                       const float* __restrict__ mean, const float* __restrict__ logvar,
                       const float* __restrict__ z, const float* __restrict__ lw,
                       const float* __restrict__ lb, const float* __restrict__ gn,
                       float* __restrict__ out) {
    __shared__ float gA[256], gB[256], gCa[256], gCb[256], rsh[256];
    __shared__ float feat[64], prob[288], sw[16];
    const int tid = threadIdx.x;   // 256

    if (blockIdx.x < 120) {
        // ---- commut pair ----
        int p = blockIdx.x;
        const int j = blockIdx.x;
        int a = 0;
        while (p >= 15 - a) { p -= 15 - a; a++; }
        const int b2 = a + 1 + p;
        const int r = tid >> 4, s = tid & 15;

        gA[tid] = ge[a * 256 + tid];
        gB[tid] = ge[b2 * 256 + tid];
        {
            int c = tid >> 4, ss = tid & 15;
            gCa[tid] = ge[(c * 16) * 256 + a * 16 + ss];
            gCb[tid] = ge[(c * 16) * 256 + b2 * 16 + ss];
        }
        __syncthreads();

        float R1 = 0.f, R2 = 0.f;
        #pragma unroll
        for (int cc = 0; cc < 16; cc++) {
            R1 += gA[r * 16 + cc] * gCb[cc * 16 + s];
            R2 += gB[r * 16 + cc] * gCa[cc * 16 + s];
        }
        float d = R1 - R2;
        rsh[tid] = d * d;
        __syncthreads();
        for (int off = 128; off > 0; off >>= 1) {
            if (tid < off) rsh[tid] += rsh[tid + off];
            __syncthreads();
        }
        if (tid == 0) atomicAdd(&g_acc[3], (double)(2.0f * rsh[0]) * (double)(120 - j));
    } else {
        // ---- head row b ----
        const int b = blockIdx.x - 120;
        const int t = tid;

        if (t < 64) {
            float v;
            if (t < 16)       v = mean[b * 16 + t];
            else if (t < 32)  v = expf(0.5f * logvar[b * 16 + (t - 16)]);
            else if (t < 48)  v = mean[(64 + b) * 16 + (t - 32)];
            else              v = expf(0.5f * mean[(64 + b) * 16 + (t - 48)]);
            feat[t] = v;
        }
        __syncthreads();

        for (int jj = t; jj < 288; jj += 256) {
            float acc = lb[jj];
            const float* wrow = lw + jj * 64;
            #pragma unroll
            for (int k = 0; k < 64; k++) acc += feat[k] * wrow[k];
            prob[jj] = acc;
        }
        __syncthreads();

        if (t < 16) {
            const int s = t;
            float l0 = prob[2 * s], l1 = prob[2 * s + 1];
            float m = fmaxf(l0, l1);
            float e0 = expf(l0 - m), e1 = expf(l1 - m);
            float Z = e0 + e1;
            float p0 = e0 / Z, p1 = e1 / Z;
            float mm = fmaxf(p0, p1);
            float lse = mm + logf(expf(p0 - mm) + expf(p1 - mm));
            float zd = z[b * 16 + s] - z[(64 + b) * 16 + s];
            int tgt = (fabsf(zd) > 0.2f) ? 1 : 0;
            float lst = (tgt ? p1 : p0) - lse;
            atomicAdd(&g_acc[4], (double)(-lst));
            float g0 = gn[(b * 16 + s) * 2], g1 = gn[(b * 16 + s) * 2 + 1];
            const float TAUF = 0.0001f;
            float d0 = (l0 + g0) / TAUF, d1 = (l1 + g1) / TAUF;
            float m2 = fmaxf(d0, d1);
            float a0 = expf(d0 - m2), a1 = expf(d1 - m2);
            float attn1 = a1 / (a0 + a1);
            sw[s] = attn1;
            out[OFF_ATT + b * 272 + s] = attn1;
        }
        __syncthreads();

        if (t < 16) {
            const int s = t;
            float mx = -1e30f;
            #pragma unroll
            for (int u = 0; u < 16; u++) mx = fmaxf(mx, prob[32 + s * 16 + u]);
            float ex[16];
            float sum = 0.f;
            #pragma unroll
            for (int u = 0; u < 16; u++) {
                ex[u] = expf(prob[32 + s * 16 + u] - mx);
                sum += ex[u];
            }
            float inv = 1.0f / sum;
            float swv = sw[s];
            #pragma unroll
            for (int u = 0; u < 16; u++) {
                float f = ex[u] * inv;
                out[OFF_ATT + b * 272 + 16 + s * 16 + u] = f;
                g_w[b * 256 + s * 16 + u] = f * swv;
            }
        }
    }
}

// ---------------------------------------------------------------------------
// sub_syms[b,s] = sum_u w[b,s*16+u]*ge[s*16+u]; S[b] = sum_s sub_syms[b,s].
__global__ void k_subsyms(const float* __restrict__ ge, float* __restrict__ out) {
    const int b = blockIdx.x, tid = threadIdx.x;  // 256 threads
    __shared__ float wsh[256];
    wsh[tid] = g_w[b * 256 + tid];
    __syncthreads();

    float Sacc = 0.f;
    #pragma unroll 1
    for (int s = 0; s < 16; s++) {
        float a = 0.f;
        #pragma unroll
        for (int u = 0; u < 16; u++)
            a += wsh[s * 16 + u] * ge[(s * 16 + u) * 256 + tid];
        out[OFF_SUB + b * 4096 + s * 256 + tid] = a;
        Sacc += a;
    }
    g_S[b * 256 + tid] = Sacc;
}

// ---------------------------------------------------------------------------
// tz1/tz2 and equivariant.
__global__ void k_tz(const float* __restrict__ z, float* __restrict__ out) {
    __shared__ float rsh[1024];
    const int t = threadIdx.x;  // 1024 threads
    const int b = t >> 4, d = t & 15;
    const float* fwd = out + OFF_FWD;

    float t1 = 0.f, t2 = 0.f;
    #pragma unroll
    for (int k = 0; k < 16; k++) {
        t1 += z[b * 16 + k] * fwd[b * 256 + k * 16 + d];
        t2 += z[(64 + b) * 16 + k] * g_inv[b * 256 + k * 16 + d];
    }
    out[OFF_TZ1 + b * 16 + d] = t1;
    out[OFF_TZ2 + b * 16 + d] = t2;

    float e1 = t2 - z[b * 16 + d];
    float e2 = t1 - z[(64 + b) * 16 + d];
    rsh[t] = e1 * e1 + e2 * e2;
    __syncthreads();
    for (int off = 512; off > 0; off >>= 1) {
        if (t < off) rsh[t] += rsh[t + off];
        __syncthreads();
    }
    if (t == 0) out[OFF_EQ] = rsh[0] * (1.0f / 1024.0f);
}

// ---------------------------------------------------------------------------
__global__ void k_final(float* __restrict__ out) {
    if (threadIdx.x == 0) {
        out[OFF_SPA]  = (float)(g_acc[0] / 32768.0);
        out[OFF_PAR]  = (float)(g_acc[1] / 67108864.0);
        out[OFF_ORTH] = (float)(g_acc[2] / 4194304.0);
        out[OFF_COM]  = (float)(g_acc[3] / 16777216.0);
        out[OFF_SEC]  = (float)(g_acc[4] / 64.0);
    }
}

// ---------------------------------------------------------------------------
extern "C" void kernel_launch(void* const* d_in, const int* in_sizes, int n_in,
                              void* d_out, int out_size) {
    const float* mean   = (const float*)d_in[0];
    const float* logvar = (const float*)d_in[1];
    const float* z      = (const float*)d_in[2];
    const float* ge     = (const float*)d_in[3];
    const float* lw     = (const float*)d_in[4];
    const float* lb     = (const float*)d_in[5];
    const float* gn     = (const float*)d_in[6];
    const int*   sidx   = (const int*)d_in[7];
    float* out = (float*)d_out;

    k_expm_ge<<<256, 256>>>(ge);                 // syms = expm(ge) + acc zero
    k_diff<<<256, 128>>>(z);                     // diff, sparse, normalize
    k_gram<<<2296, 256>>>(sidx);                 // parallel + orth
    k_misc<<<184, 256>>>(ge, mean, logvar, z, lw, lb, gn, out);  // commut + head
    k_subsyms<<<64, 256>>>(ge, out);             // sub_syms + S
    k_expm_S<<<128, 256>>>(out);                 // fwd_syms + inv_syms
    k_tz<<<1, 1024>>>(z, out);                   // tz1, tz2, equivariant
    k_final<<<1, 32>>>(out);                     // scalars
}

// round 5
// speedup vs baseline: 2.0226x; 1.4570x over previous
#include <cuda_runtime.h>

// Problem constants
#define DIMN   16
#define SECN   16
#define SUBN   16
#define EN     256
#define BATCHN 128
#define SLN    64

// Output layout (flattened reference tuple, float32)
#define OFF_TZ1  0
#define OFF_TZ2  1024
#define OFF_FWD  2048
#define OFF_EQ   18432
#define OFF_ATT  18433
#define OFF_ORTH 35841
#define OFF_PAR  35842
#define OFF_COM  35843
#define OFF_SPA  35844
#define OFF_SEC  35845
#define OFF_SUB  35846

// Scratch
__device__ float  g_syms[EN * 256];            // expm(ge)
__device__ float  g_u[EN * BATCHN * DIMN];     // normalized diff rows
__device__ float  g_w[SLN * EN];               // switch*fprob weights
__device__ float  g_S[SLN * 256];              // S matrices
__device__ float  g_inv[SLN * 256];            // expm(-S)
__device__ double g_acc[8] = {0};              // 0 sparse 1 parallel 2 orth 3 commut 4 sector
                                               // zero at load; K4 re-zeroes after consuming

// ---------------------------------------------------------------------------
// f32x2 packed helpers
__device__ __forceinline__ unsigned long long pk2(float lo, float hi) {
    unsigned long long r;
    asm("mov.b64 %0, {%1, %2};" : "=l"(r) : "f"(lo), "f"(hi));
    return r;
}
__device__ __forceinline__ void upk2(float& lo, float& hi, unsigned long long v) {
    asm("mov.b64 {%0, %1}, %2;" : "=f"(lo), "=f"(hi) : "l"(v));
}
__device__ __forceinline__ unsigned long long ffma2(unsigned long long a,
                                                    unsigned long long b,
                                                    unsigned long long c) {
    unsigned long long d;
    asm("fma.rn.f32x2 %0, %1, %2, %3;" : "=l"(d) : "l"(a), "l"(b), "l"(c));
    return d;
}

// ---------------------------------------------------------------------------
// expm of one 16x16 matrix per block (256 threads): scaling & squaring +
// order-12 Taylor Horner, ping-pong buffers (1 sync per matmul).
// sm must hold >= 784 floats.
__device__ __forceinline__ void expm_body(const float* __restrict__ src,
                                          float* __restrict__ dst, float sign,
                                          float* sm) {
    float* Bm  = sm;
    float* Pa  = sm + 256;
    float* Pb  = sm + 512;
    float* red = sm + 768;   // 16
    __shared__ int s_sh;
    const int tid = threadIdx.x;
    const int r = tid >> 4, c = tid & 15;

    float a = sign * src[tid];

    Pb[tid] = fabsf(a);
    __syncthreads();
    if (tid < 16) {
        float rs = 0.f;
        #pragma unroll
        for (int k = 0; k < 16; k++) rs += Pb[tid * 16 + k];
        red[tid] = rs;
    }
    __syncthreads();
    if (tid == 0) {
        float mx = 0.f;
        #pragma unroll
        for (int k = 0; k < 16; k++) mx = fmaxf(mx, red[k]);
        int s = 0;
        while (mx > 0.25f && s < 48) { mx *= 0.5f; s++; }
        s_sh = s;
    }
    __syncthreads();
    const int s = s_sh;

    float b = a * exp2f(-(float)s);
    Bm[tid] = b;
    const float eye = (r == c) ? 1.0f : 0.0f;
    float res = b * (1.0f / 12.0f) + eye;
    Pa[tid] = res;

    float* cur = Pa;
    float* nxt = Pb;
    for (int k = 11; k >= 1; k--) {
        __syncthreads();
        float acc = 0.f;
        #pragma unroll
        for (int j = 0; j < 16; j++) acc += Bm[r * 16 + j] * cur[j * 16 + c];
        res = acc * (1.0f / (float)k) + eye;
        nxt[tid] = res;
        float* t_ = cur; cur = nxt; nxt = t_;
    }
    for (int i = 0; i < s; i++) {
        __syncthreads();
        float acc = 0.f;
        #pragma unroll
        for (int j = 0; j < 16; j++) acc += cur[r * 16 + j] * cur[j * 16 + c];
        res = acc;
        nxt[tid] = res;
        float* t_ = cur; cur = nxt; nxt = t_;
    }
    dst[tid] = res;
}

// ---------------------------------------------------------------------------
// K1: blocks [0,256) expm(ge); [256,376) commut pairs; [376,440) head rows.
__global__ void __launch_bounds__(256) k_front(
        const float* __restrict__ ge,
        const float* __restrict__ mean, const float* __restrict__ logvar,
        const float* __restrict__ z, const float* __restrict__ lw,
        const float* __restrict__ lb, const float* __restrict__ gn,
        float* __restrict__ out) {
    __shared__ float sm[1300];
    const int tid = threadIdx.x;
    const int blk = blockIdx.x;

    if (blk < 256) {
        expm_body(ge + blk * 256, g_syms + blk * 256, 1.0f, sm);
    } else if (blk < 376) {
        // ---- commut pair j = blk-256 ----
        float* gA  = sm;
        float* gB  = sm + 256;
        float* gCa = sm + 512;
        float* gCb = sm + 768;
        float* rsh = sm + 1024;
        const int j = blk - 256;
        int p = j;
        int a = 0;
        while (p >= 15 - a) { p -= 15 - a; a++; }
        const int b2 = a + 1 + p;
        const int r = tid >> 4, s = tid & 15;

        gA[tid] = ge[a * 256 + tid];
        gB[tid] = ge[b2 * 256 + tid];
        {
            int c = tid >> 4, ss = tid & 15;
            gCa[tid] = ge[(c * 16) * 256 + a * 16 + ss];
            gCb[tid] = ge[(c * 16) * 256 + b2 * 16 + ss];
        }
        __syncthreads();

        float R1 = 0.f, R2 = 0.f;
        #pragma unroll
        for (int cc = 0; cc < 16; cc++) {
            R1 += gA[r * 16 + cc] * gCb[cc * 16 + s];
            R2 += gB[r * 16 + cc] * gCa[cc * 16 + s];
        }
        float d = R1 - R2;
        rsh[tid] = d * d;
        __syncthreads();
        for (int off = 128; off > 0; off >>= 1) {
            if (tid < off) rsh[tid] += rsh[tid + off];
            __syncthreads();
        }
        if (tid == 0) atomicAdd(&g_acc[3], (double)(2.0f * rsh[0]) * (double)(120 - j));
    } else {
        // ---- head row b = blk-376 ----
        float* feat = sm;          // 64
        float* prob = sm + 64;     // 288
        float* sw   = sm + 352;    // 16
        const int b = blk - 376;
        const int t = tid;

        if (t < 64) {
            float v;
            if (t < 16)       v = mean[b * 16 + t];
            else if (t < 32)  v = expf(0.5f * logvar[b * 16 + (t - 16)]);
            else if (t < 48)  v = mean[(64 + b) * 16 + (t - 32)];
            else              v = expf(0.5f * mean[(64 + b) * 16 + (t - 48)]);
            feat[t] = v;
        }
        __syncthreads();

        // warp-per-row GEMV: coalesced lw reads + shfl reduction
        {
            const int w = t >> 5, lane = t & 31;
            const float f0 = feat[lane], f1 = feat[lane + 32];
            for (int jj = w; jj < 288; jj += 8) {
                const float* wrow = lw + jj * 64;
                float acc = wrow[lane] * f0 + wrow[lane + 32] * f1;
                acc += __shfl_down_sync(0xffffffffu, acc, 16);
                acc += __shfl_down_sync(0xffffffffu, acc, 8);
                acc += __shfl_down_sync(0xffffffffu, acc, 4);
                acc += __shfl_down_sync(0xffffffffu, acc, 2);
                acc += __shfl_down_sync(0xffffffffu, acc, 1);
                if (lane == 0) prob[jj] = acc + lb[jj];
            }
        }
        __syncthreads();

        if (t < 16) {
            const int s = t;
            float l0 = prob[2 * s], l1 = prob[2 * s + 1];
            float m = fmaxf(l0, l1);
            float e0 = expf(l0 - m), e1 = expf(l1 - m);
            float Z = e0 + e1;
            float p0 = e0 / Z, p1 = e1 / Z;
            float mm = fmaxf(p0, p1);
            float lse = mm + logf(expf(p0 - mm) + expf(p1 - mm));
            float zd = z[b * 16 + s] - z[(64 + b) * 16 + s];
            int tgt = (fabsf(zd) > 0.2f) ? 1 : 0;
            float v = -((tgt ? p1 : p0) - lse);
            // reduce 16 lanes -> 1 atomic
            v += __shfl_down_sync(0x0000ffffu, v, 8);
            v += __shfl_down_sync(0x0000ffffu, v, 4);
            v += __shfl_down_sync(0x0000ffffu, v, 2);
            v += __shfl_down_sync(0x0000ffffu, v, 1);
            if (s == 0) atomicAdd(&g_acc[4], (double)v);

            float g0 = gn[(b * 16 + s) * 2], g1 = gn[(b * 16 + s) * 2 + 1];
            const float TAUF = 0.0001f;
            float d0 = (l0 + g0) / TAUF, d1 = (l1 + g1) / TAUF;
            float m2 = fmaxf(d0, d1);
            float a0 = expf(d0 - m2), a1 = expf(d1 - m2);
            float attn1 = a1 / (a0 + a1);
            sw[s] = attn1;
            out[OFF_ATT + b * 272 + s] = attn1;
        }
        __syncthreads();

        if (t < 16) {
            const int s = t;
            float mx = -1e30f;
            #pragma unroll
            for (int u = 0; u < 16; u++) mx = fmaxf(mx, prob[32 + s * 16 + u]);
            float ex[16];
            float sum = 0.f;
            #pragma unroll
            for (int u = 0; u < 16; u++) {
                ex[u] = expf(prob[32 + s * 16 + u] - mx);
                sum += ex[u];
            }
            float inv = 1.0f / sum;
            float swv = sw[s];
            #pragma unroll
            for (int u = 0; u < 16; u++) {
                float f = ex[u] * inv;
                out[OFF_ATT + b * 272 + 16 + s * 16 + u] = f;
                g_w[b * 256 + s * 16 + u] = f * swv;
            }
        }
    }
}

// ---------------------------------------------------------------------------
// K2: blocks [0,128) diff (2 group-elements per block); [128,192) subsyms.
__global__ void __launch_bounds__(256) k_mid(const float* __restrict__ z,
                                             const float* __restrict__ ge,
                                             float* __restrict__ out) {
    __shared__ float sm[2816];
    const int tid = threadIdx.x;
    const int blk = blockIdx.x;

    if (blk < 128) {
        float* sy    = sm;          // 512 (two 16x16)
        float* zsh   = sm + 512;    // 2048
        float* redsh = sm + 2560;   // 256

        sy[tid] = g_syms[blk * 512 + tid];
        sy[tid + 256] = g_syms[blk * 512 + 256 + tid];
        #pragma unroll
        for (int i = 0; i < 8; i++) zsh[tid + 256 * i] = z[tid + 256 * i];
        __syncthreads();

        const int half = tid >> 7, b = tid & 127;
        const float* syp = sy + half * 256;
        float zr[16];
        #pragma unroll
        for (int d = 0; d < 16; d++) zr[d] = zsh[b * 16 + d];

        float dv[16];
        float s2 = 0.f, mx = 0.f;
        #pragma unroll
        for (int d = 0; d < 16; d++) {
            float dot0 = 0.f, dot1 = 0.f;
            #pragma unroll
            for (int k = 0; k < 16; k += 2) {
                dot0 += zr[k] * syp[k * 16 + d];
                dot1 += zr[k + 1] * syp[(k + 1) * 16 + d];
            }
            float v = zr[d] - (dot0 + dot1);
            dv[d] = v;
            float q = v * v;
            s2 += q;
            mx = fmaxf(mx, q);
        }
        float sp = s2 - mx;
        sp = sp * sp;

        redsh[tid] = sp;
        __syncthreads();
        for (int off = 128; off > 0; off >>= 1) {
            if (tid < off) redsh[tid] += redsh[tid + off];
            __syncthreads();
        }
        if (tid == 0) atomicAdd(&g_acc[0], (double)redsh[0]);

        const float inv = rsqrtf(s2);
        float* dstu = g_u + ((blk * 2 + half) * 128 + b) * 16;
        #pragma unroll
        for (int d = 0; d < 16; d++) dstu[d] = dv[d] * inv;
    } else {
        // ---- subsyms b = blk-128 ----
        float* wsh = sm;
        const int b = blk - 128;
        wsh[tid] = g_w[b * 256 + tid];
        __syncthreads();

        float Sacc = 0.f;
        #pragma unroll 1
        for (int s = 0; s < 16; s++) {
            float a = 0.f;
            #pragma unroll
            for (int u = 0; u < 16; u++)
                a += wsh[s * 16 + u] * ge[(s * 16 + u) * 256 + tid];
            out[OFF_SUB + b * 4096 + s * 256 + tid] = a;
            Sacc += a;
        }
        g_S[b * 256 + tid] = Sacc;
    }
}

// ---------------------------------------------------------------------------
// K3: blocks [0,128) expm(+/-S); blocks [128,2424) gram tiles.
__global__ void __launch_bounds__(256) k_back(const int* __restrict__ sidx,
                                              float* __restrict__ out) {
    __shared__ float sm[4352];
    const int tid = threadIdx.x;

    if (blockIdx.x < 128) {
        const int b = blockIdx.x & 63;
        const bool inv = blockIdx.x >= 64;
        float* dst = inv ? (g_inv + b * 256) : (out + OFF_FWD + b * 256);
        expm_body(g_S + b * 256, dst, inv ? -1.0f : 1.0f, sm);
        return;
    }

    float* As  = sm;
    float* Bs  = sm + 2048;
    float* rsh = sm + 4096;
    const int bi = blockIdx.x - 128;
    const bool isOrth = bi >= 2176;

    const float* baseA;
    const float* baseB;
    float mult;
    if (!isOrth) {
        const int sec = bi / 136;
        int p = bi % 136;
        int ti = 0;
        while (p >= 16 - ti) { p -= 16 - ti; ti++; }
        const int tj = ti + p;
        baseA = g_u + (sec * 2048 + ti * 128) * 16;
        baseB = g_u + (sec * 2048 + tj * 128) * 16;
        mult = (ti == tj) ? 1.0f : 2.0f;
    } else {
        int p = bi - 2176;
        int s = 0;
        while (p >= 15 - s) { p -= 15 - s; s++; }
        const int t2 = s + 1 + p;
        baseA = g_u + (s * 16 + sidx[s]) * 2048;
        baseB = g_u + (t2 * 16 + sidx[t2]) * 2048;
        mult = 2.0f;
    }

    // Load both 128x16 tiles transposed to [k][m].
    {
        const float4* a4 = (const float4*)baseA;
        const float4* b4 = (const float4*)baseB;
        #pragma unroll
        for (int i = 0; i < 2; i++) {
            const int idx = tid * 2 + i;
            const float4 va = a4[idx];
            const float4 vb = b4[idx];
            const int m = idx >> 2;
            const int k = (idx & 3) * 4;
            As[(k + 0) * 128 + m] = va.x; As[(k + 1) * 128 + m] = va.y;
            As[(k + 2) * 128 + m] = va.z; As[(k + 3) * 128 + m] = va.w;
            Bs[(k + 0) * 128 + m] = vb.x; Bs[(k + 1) * 128 + m] = vb.y;
            Bs[(k + 2) * 128 + m] = vb.z; Bs[(k + 3) * 128 + m] = vb.w;
        }
    }
    __syncthreads();

    const int tx = tid & 15, ty = tid >> 4;
    unsigned long long acc[8][4];
    #pragma unroll
    for (int m = 0; m < 8; m++)
        #pragma unroll
        for (int n = 0; n < 4; n++) acc[m][n] = 0ULL;

    #pragma unroll
    for (int k = 0; k < 16; k++) {
        const float4 a0 = *(const float4*)(As + k * 128 + ty * 8);
        const float4 a1 = *(const float4*)(As + k * 128 + ty * 8 + 4);
        const float4 b0 = *(const float4*)(Bs + k * 128 + tx * 8);
        const float4 b1 = *(const float4*)(Bs + k * 128 + tx * 8 + 4);
        unsigned long long bp[4];
        bp[0] = pk2(b0.x, b0.y); bp[1] = pk2(b0.z, b0.w);
        bp[2] = pk2(b1.x, b1.y); bp[3] = pk2(b1.z, b1.w);
        const float av[8] = {a0.x, a0.y, a0.z, a0.w, a1.x, a1.y, a1.z, a1.w};
        #pragma unroll
        for (int m = 0; m < 8; m++) {
            const unsigned long long am = pk2(av[m], av[m]);
            #pragma unroll
            for (int n = 0; n < 4; n++) acc[m][n] = ffma2(am, bp[n], acc[m][n]);
        }
    }

    float local = 0.f;
    #pragma unroll
    for (int m = 0; m < 8; m++) {
        float l0, h0, l1, h1, l2, h2, l3, h3;
        upk2(l0, h0, acc[m][0]); upk2(l1, h1, acc[m][1]);
        upk2(l2, h2, acc[m][2]); upk2(l3, h3, acc[m][3]);
        if (isOrth) {
            local += l0 * l0 + h0 * h0 + l1 * l1 + h1 * h1
                   + l2 * l2 + h2 * h2 + l3 * l3 + h3 * h3;
        } else {
            // fuse 4 logs into 1: factors >= 1e-9 so product >= 1e-36 > FLT_MIN
            float p0 = fmaf(l0, l0, 1e-9f) * fmaf(h0, h0, 1e-9f)
                     * fmaf(l1, l1, 1e-9f) * fmaf(h1, h1, 1e-9f);
            float p1 = fmaf(l2, l2, 1e-9f) * fmaf(h2, h2, 1e-9f)
                     * fmaf(l3, l3, 1e-9f) * fmaf(h3, h3, 1e-9f);
            local -= __logf(p0) + __logf(p1);
        }
    }
    local *= mult;

    rsh[tid] = local;
    __syncthreads();
    for (int off = 128; off > 0; off >>= 1) {
        if (tid < off) rsh[tid] += rsh[tid + off];
        __syncthreads();
    }
    if (tid == 0) atomicAdd(&g_acc[isOrth ? 2 : 1], (double)rsh[0]);
}

// ---------------------------------------------------------------------------
// K4: tz1/tz2 + equivariant + finalize scalars + reset accumulators.
__global__ void k_tail(const float* __restrict__ z, float* __restrict__ out) {
    __shared__ float rsh[1024];
    const int t = threadIdx.x;  // 1024 threads
    const int b = t >> 4, d = t & 15;
    const float* fwd = out + OFF_FWD;

    float t1 = 0.f, t2 = 0.f;
    #pragma unroll
    for (int k = 0; k < 16; k++) {
        t1 += z[b * 16 + k] * fwd[b * 256 + k * 16 + d];
        t2 += z[(64 + b) * 16 + k] * g_inv[b * 256 + k * 16 + d];
    }
    out[OFF_TZ1 + b * 16 + d] = t1;
    out[OFF_TZ2 + b * 16 + d] = t2;

    float e1 = t2 - z[b * 16 + d];
    float e2 = t1 - z[(64 + b) * 16 + d];
    rsh[t] = e1 * e1 + e2 * e2;
    __syncthreads();
    for (int off = 512; off > 0; off >>= 1) {
        if (t < off) rsh[t] += rsh[t + off];
        __syncthreads();
    }
    if (t == 0) {
        out[OFF_EQ]   = rsh[0] * (1.0f / 1024.0f);
        out[OFF_SPA]  = (float)(g_acc[0] / 32768.0);
        out[OFF_PAR]  = (float)(g_acc[1] / 67108864.0);
        out[OFF_ORTH] = (float)(g_acc[2] / 4194304.0);
        out[OFF_COM]  = (float)(g_acc[3] / 16777216.0);
        out[OFF_SEC]  = (float)(g_acc[4] / 64.0);
        #pragma unroll
        for (int i = 0; i < 8; i++) g_acc[i] = 0.0;   // ready for next replay
    }
}

// ---------------------------------------------------------------------------
extern "C" void kernel_launch(void* const* d_in, const int* in_sizes, int n_in,
                              void* d_out, int out_size) {
    const float* mean   = (const float*)d_in[0];
    const float* logvar = (const float*)d_in[1];
    const float* z      = (const float*)d_in[2];
    const float* ge     = (const float*)d_in[3];
    const float* lw     = (const float*)d_in[4];
    const float* lb     = (const float*)d_in[5];
    const float* gn     = (const float*)d_in[6];
    const int*   sidx   = (const int*)d_in[7];
    float* out = (float*)d_out;

    k_front<<<440, 256>>>(ge, mean, logvar, z, lw, lb, gn, out); // expm(ge)+commut+head
    k_mid<<<192, 256>>>(z, ge, out);                             // diff+sparse+subsyms
    k_back<<<2424, 256>>>(sidx, out);                            // expm(+/-S)+gram
    k_tail<<<1, 1024>>>(z, out);                                 // tz+finalize+reset
}